// round 11
// baseline (speedup 1.0000x reference)
#include <cuda_runtime.h>
#include <cstdint>
#include <cstddef>

// ---------------------------------------------------------------------------
// Problem dims
// ---------------------------------------------------------------------------
#define B_DIM   64
#define IN_DIM  1024
#define OUT_DIM 1024
#define E_DIM   8
#define H_DIM   8

// GEMM tiling: D[o=128, b=64] per CTA; K split 2-ways; per expert.
// Grid = 8 m-tiles x 8 experts x 2 k-splits = 128 CTAs (one wave on 148 SMs).
#define M_TILE       128
#define N_TILE       64
#define KSPLIT       2
#define K_PER        (IN_DIM / KSPLIT)     // 512
#define CHUNK_K      32
#define NCHUNK       (K_PER / CHUNK_K)     // 16
#define GEMM_THREADS 256

// Permuted smem layout: within a 32-k chunk, element at (row, k) lives at
// word  row*SA + (k&3)*8 + (k>>2).  Fragments for 4 consecutive k-steps are a
// contiguous 16B run (lds.128); SA=36 keeps consumers bank-conflict-free.
#define SA           36                     // smem row stride in words
#define A_STG_WORDS  (M_TILE * SA)          // 4608
#define B_STG_WORDS  (N_TILE * SA)          // 2304
#define SMEM_BYTES   ((2 * A_STG_WORDS + 2 * B_STG_WORDS) * 4)  // 55296

// ---------------------------------------------------------------------------
// Device scratch (allocation-free rule: static globals)
// ---------------------------------------------------------------------------
__device__ float g_pooled[B_DIM];                                 // mean(x,row)
__device__ float g_part[8 * E_DIM * KSPLIT * M_TILE * N_TILE];    // 4 MB partials

// ---------------------------------------------------------------------------
// Helpers
// ---------------------------------------------------------------------------
__device__ __forceinline__ float to_tf32(float x) {
    // round-to-nearest tf32 (unbiased; truncation would give ~1e-3 bias)
    uint32_t u;
    asm("cvt.rna.tf32.f32 %0, %1;" : "=r"(u) : "f"(x));
    return __uint_as_float(u);
}

__device__ __forceinline__ void mma_tf32(float* d,
                                         uint32_t a0, uint32_t a1,
                                         uint32_t a2, uint32_t a3,
                                         uint32_t b0, uint32_t b1) {
    asm volatile(
        "mma.sync.aligned.m16n8k8.row.col.f32.tf32.tf32.f32 "
        "{%0,%1,%2,%3}, {%4,%5,%6,%7}, {%8,%9}, {%0,%1,%2,%3};"
        : "+f"(d[0]), "+f"(d[1]), "+f"(d[2]), "+f"(d[3])
        : "r"(a0), "r"(a1), "r"(a2), "r"(a3), "r"(b0), "r"(b1));
}

// ---------------------------------------------------------------------------
// Kernel 1: tf32 mma.sync GEMM, partials to g_part, plus distributed pooling
// ---------------------------------------------------------------------------
struct StgRegs {
    float4 a[2][2];   // 2 A-groups x (8 consecutive k as lo/hi float4)
    float4 b[2];      // 1 B-group
};

__device__ __forceinline__ void ldg_chunk(const float* __restrict__ Abase,
                                          const float* __restrict__ Bbase,
                                          int k0, int tid, StgRegs& R) {
    #pragma unroll
    for (int i = 0; i < 2; ++i) {
        int gi = tid + (i << 8);            // 0..511 : A groups (row, 8-k group)
        int row = gi >> 2, j8 = gi & 3;
        const float4* p = reinterpret_cast<const float4*>(
            Abase + (size_t)row * IN_DIM + k0 + j8 * 8);
        R.a[i][0] = p[0];
        R.a[i][1] = p[1];
    }
    {
        int row = tid >> 2, j8 = tid & 3;   // 0..255 : B groups
        const float4* p = reinterpret_cast<const float4*>(
            Bbase + (size_t)row * IN_DIM + k0 + j8 * 8);
        R.b[0] = p[0];
        R.b[1] = p[1];
    }
}

// cols j8*8 + c (c=0..7) -> permuted word (c&3)*8 + 2*j8 + (c>=4)
// => pairs {lo.c, hi.c} at word base + c*8, base = row*SA + 2*j8 (8B aligned).
__device__ __forceinline__ void cvt_sts(float* __restrict__ As,
                                        float* __restrict__ Bs,
                                        int tid, const StgRegs& R) {
    #pragma unroll
    for (int i = 0; i < 2; ++i) {
        int gi = tid + (i << 8);
        int row = gi >> 2, j8 = gi & 3;
        float* base = As + row * SA + 2 * j8;
        float4 lo = R.a[i][0], hi = R.a[i][1];
        *reinterpret_cast<float2*>(base +  0) = make_float2(to_tf32(lo.x), to_tf32(hi.x));
        *reinterpret_cast<float2*>(base +  8) = make_float2(to_tf32(lo.y), to_tf32(hi.y));
        *reinterpret_cast<float2*>(base + 16) = make_float2(to_tf32(lo.z), to_tf32(hi.z));
        *reinterpret_cast<float2*>(base + 24) = make_float2(to_tf32(lo.w), to_tf32(hi.w));
    }
    {
        int row = tid >> 2, j8 = tid & 3;
        float* base = Bs + row * SA + 2 * j8;
        float4 lo = R.b[0], hi = R.b[1];
        *reinterpret_cast<float2*>(base +  0) = make_float2(to_tf32(lo.x), to_tf32(hi.x));
        *reinterpret_cast<float2*>(base +  8) = make_float2(to_tf32(lo.y), to_tf32(hi.y));
        *reinterpret_cast<float2*>(base + 16) = make_float2(to_tf32(lo.z), to_tf32(hi.z));
        *reinterpret_cast<float2*>(base + 24) = make_float2(to_tf32(lo.w), to_tf32(hi.w));
    }
}

__device__ __forceinline__ void compute_chunk(const float* __restrict__ As,
                                              const float* __restrict__ Bs,
                                              int wm32, int wn32, int g, int t,
                                              float acc[2][4][4]) {
    #pragma unroll
    for (int kp = 0; kp < 2; ++kp) {        // k-step pairs (2 x k8 each)
        uint4 A4[2][2], B4[4];
        #pragma unroll
        for (int mm = 0; mm < 2; ++mm)
            #pragma unroll
            for (int h = 0; h < 2; ++h)
                A4[mm][h] = *reinterpret_cast<const uint4*>(
                    As + (wm32 + mm * 16 + g + 8 * h) * SA + t * 8 + kp * 4);
        #pragma unroll
        for (int nt = 0; nt < 4; ++nt)
            B4[nt] = *reinterpret_cast<const uint4*>(
                Bs + (wn32 + nt * 8 + g) * SA + t * 8 + kp * 4);
        #pragma unroll
        for (int k2 = 0; k2 < 2; ++k2) {
            #pragma unroll
            for (int mm = 0; mm < 2; ++mm) {
                uint32_t a0 = k2 ? A4[mm][0].z : A4[mm][0].x;
                uint32_t a2 = k2 ? A4[mm][0].w : A4[mm][0].y;
                uint32_t a1 = k2 ? A4[mm][1].z : A4[mm][1].x;
                uint32_t a3 = k2 ? A4[mm][1].w : A4[mm][1].y;
                #pragma unroll
                for (int nt = 0; nt < 4; ++nt) {
                    uint32_t b0 = k2 ? B4[nt].z : B4[nt].x;
                    uint32_t b1 = k2 ? B4[nt].w : B4[nt].y;
                    mma_tf32(acc[mm][nt], a0, a1, a2, a3, b0, b1);
                }
            }
        }
    }
}

__global__ void __launch_bounds__(GEMM_THREADS, 1)
gemm_kernel(const float* __restrict__ x, const float* __restrict__ weight) {
    extern __shared__ float smem[];
    float* Abuf[2] = { smem, smem + A_STG_WORDS };
    float* Bbuf[2] = { smem + 2 * A_STG_WORDS,
                       smem + 2 * A_STG_WORDS + B_STG_WORDS };

    int tid = threadIdx.x;
    int wid = tid >> 5, lid = tid & 31;
    int g = lid >> 2, t = lid & 3;
    int wm32 = (wid >> 1) * 32;     // warp M offset (4 warps over M)
    int wn32 = (wid & 1) * 32;      // warp N offset (2 warps over N)

    int m = blockIdx.x, e = blockIdx.y, ks = blockIdx.z;
    const float* Abase = weight + ((size_t)e << 20)
                       + (size_t)m * (M_TILE * IN_DIM) + (size_t)ks * K_PER;
    const float* Bbase = x + (size_t)ks * K_PER;

    float acc[2][4][4];
    #pragma unroll
    for (int mm = 0; mm < 2; ++mm)
        #pragma unroll
        for (int nt = 0; nt < 4; ++nt)
            #pragma unroll
            for (int q = 0; q < 4; ++q) acc[mm][nt][q] = 0.f;

    StgRegs R;
    ldg_chunk(Abase, Bbase, 0, tid, R);
    cvt_sts(Abuf[0], Bbuf[0], tid, R);
    __syncthreads();

    for (int tch = 0; tch < NCHUNK; ++tch) {
        if (tch + 1 < NCHUNK)
            ldg_chunk(Abase, Bbase, (tch + 1) * CHUNK_K, tid, R);
        compute_chunk(Abuf[tch & 1], Bbuf[tch & 1], wm32, wn32, g, t, acc);
        if (tch + 1 < NCHUNK) {
            cvt_sts(Abuf[(tch + 1) & 1], Bbuf[(tch + 1) & 1], tid, R);
            __syncthreads();
        }
    }

    // Epilogue: unscaled partial to g_part[m][e][ks][ol][b]
    float* dst = g_part + ((size_t)((m * E_DIM + e) * KSPLIT + ks) << 13);
    #pragma unroll
    for (int mm = 0; mm < 2; ++mm) {
        #pragma unroll
        for (int nt = 0; nt < 4; ++nt) {
            int r0 = wm32 + mm * 16 + g;
            int c0 = wn32 + nt * 8 + 2 * t;
            *reinterpret_cast<float2*>(dst + (size_t)r0 * N_TILE + c0) =
                make_float2(acc[mm][nt][0], acc[mm][nt][1]);
            *reinterpret_cast<float2*>(dst + (size_t)(r0 + 8) * N_TILE + c0) =
                make_float2(acc[mm][nt][2], acc[mm][nt][3]);
        }
    }

    // Distributed pooling: the 64 CTAs with ks==1 each produce one row mean.
    // Runs after the epilogue so it overlaps other CTAs' tails; the reduce
    // kernel (next graph node) is the only consumer, so stream order suffices.
    if (ks == 1 && wid == 0) {
        int b = m * E_DIM + e;                  // 0..63, unique per (m,e)
        const float* xr = x + (size_t)b * IN_DIM;
        float s = 0.f;
        #pragma unroll 8
        for (int k = lid; k < IN_DIM; k += 32) s += xr[k];
        #pragma unroll
        for (int o = 16; o > 0; o >>= 1) s += __shfl_xor_sync(0xFFFFFFFFu, s, o);
        if (lid == 0) g_pooled[b] = s * (1.0f / IN_DIM);
    }
}

// ---------------------------------------------------------------------------
// Kernel 2: c[b,e] from g_pooled (tiny, redundant per block), then
//           y[b,o] = sum_e c[b,e] * (part[m,e,0,ol,b] + part[m,e,1,ol,b])
// ---------------------------------------------------------------------------
__global__ void reduce_kernel(float* __restrict__ y,
                              const float* __restrict__ align_conv,
                              const float* __restrict__ W_ih,
                              const float* __restrict__ b_ih,
                              const float* __restrict__ b_hh,
                              const float* __restrict__ W_att,
                              const float* __restrict__ b_att) {
    __shared__ float cs[B_DIM * E_DIM];
    int tid = threadIdx.x;
    if (tid < B_DIM) {
        float p = g_pooled[tid];
        float r[H_DIM];
        #pragma unroll
        for (int j = 0; j < H_DIM; ++j)
            r[j] = fmaxf(tanhf(p * W_ih[j] + b_ih[j] + b_hh[j]), 0.f);
        float a[E_DIM];
        float mx = -1e30f;
        #pragma unroll
        for (int eo = 0; eo < E_DIM; ++eo) {
            float s = b_att[eo];
            #pragma unroll
            for (int j = 0; j < H_DIM; ++j) s = fmaf(W_att[eo * H_DIM + j], r[j], s);
            a[eo] = s;
            mx = fmaxf(mx, s);
        }
        float se = 0.f;
        #pragma unroll
        for (int eo = 0; eo < E_DIM; ++eo) { a[eo] = expf(a[eo] - mx); se += a[eo]; }
        float inv = 1.f / se;
        #pragma unroll
        for (int eo = 0; eo < E_DIM; ++eo) {
            float ce = 0.f;
            #pragma unroll
            for (int f = 0; f < E_DIM; ++f)
                ce = fmaf(a[f] * inv, align_conv[f * E_DIM + eo], ce);
            cs[tid * E_DIM + eo] = ce;
        }
    }
    __syncthreads();

    int idx = blockIdx.x * blockDim.x + tid;   // 64 blocks * 1024 = 65536
    int o  = idx >> 6;
    int b  = idx & 63;
    int mm = o >> 7;
    int ol = o & 127;
    const float* pbase = g_part + (size_t)ol * N_TILE + b;
    float acc = 0.f;
    #pragma unroll
    for (int e = 0; e < E_DIM; ++e) {
        float w = cs[b * E_DIM + e];
        const float* p = pbase + ((size_t)((mm * E_DIM + e) * KSPLIT) << 13);
        acc = fmaf(w, p[0] + p[8192], acc);
    }
    y[b * OUT_DIM + o] = acc;
}

// ---------------------------------------------------------------------------
// Launch: 2 graph nodes (gemm -> reduce)
// ---------------------------------------------------------------------------
extern "C" void kernel_launch(void* const* d_in, const int* in_sizes, int n_in,
                              void* d_out, int out_size) {
    const float* x          = (const float*)d_in[0];
    const float* weight     = (const float*)d_in[1];
    const float* align_conv = (const float*)d_in[2];
    const float* W_ih       = (const float*)d_in[3];
    // d_in[4] = W_hh: h0 = 0, contributes nothing -- intentionally unused.
    const float* b_ih       = (const float*)d_in[5];
    const float* b_hh       = (const float*)d_in[6];
    const float* W_att      = (const float*)d_in[7];
    const float* b_att      = (const float*)d_in[8];
    float* y = (float*)d_out;

    cudaFuncSetAttribute(gemm_kernel,
                         cudaFuncAttributeMaxDynamicSharedMemorySize, SMEM_BYTES);

    gemm_kernel<<<dim3(8, E_DIM, KSPLIT), GEMM_THREADS, SMEM_BYTES>>>(x, weight);
    reduce_kernel<<<64, 1024>>>(y, align_conv, W_ih, b_ih, b_hh, W_att, b_att);
}

// round 12
// speedup vs baseline: 1.0183x; 1.0183x over previous
#include <cuda_runtime.h>
#include <cstdint>
#include <cstddef>

// ---------------------------------------------------------------------------
// Problem dims
// ---------------------------------------------------------------------------
#define B_DIM   64
#define IN_DIM  1024
#define OUT_DIM 1024
#define E_DIM   8
#define H_DIM   8

// GEMM tiling: D[o=128, b=64] per CTA; K split 2-ways; per expert.
// Grid = 8 m-tiles x 8 experts x 2 k-splits = 128 CTAs (one wave on 148 SMs).
#define M_TILE       128
#define N_TILE       64
#define KSPLIT       2
#define K_PER        (IN_DIM / KSPLIT)     // 512
#define CHUNK_K      32
#define NCHUNK       (K_PER / CHUNK_K)     // 16
#define GEMM_THREADS 256

// Permuted smem layout: within a 32-k chunk, element at (row, k) lives at
// word  row*SA + (k&3)*8 + (k>>2).  Fragments for 4 consecutive k-steps are a
// contiguous 16B run (lds.128); SA=36 keeps consumers bank-conflict-free.
#define SA           36                     // smem row stride in words
#define A_STG_WORDS  (M_TILE * SA)          // 4608
#define B_STG_WORDS  (N_TILE * SA)          // 2304
#define SMEM_BYTES   ((2 * A_STG_WORDS + 2 * B_STG_WORDS) * 4)  // 55296

// ---------------------------------------------------------------------------
// Device scratch (allocation-free rule: static globals)
// ---------------------------------------------------------------------------
__device__ float g_pooled[B_DIM];                                 // mean(x,row)
__device__ float g_part[8 * E_DIM * KSPLIT * M_TILE * N_TILE];    // 4 MB partials

// ---------------------------------------------------------------------------
// Helpers
// ---------------------------------------------------------------------------
__device__ __forceinline__ float to_tf32(float x) {
    // round-to-nearest tf32 (unbiased; truncation would give ~1e-3 bias)
    uint32_t u;
    asm("cvt.rna.tf32.f32 %0, %1;" : "=r"(u) : "f"(x));
    return __uint_as_float(u);
}

__device__ __forceinline__ void mma_tf32(float* d,
                                         uint32_t a0, uint32_t a1,
                                         uint32_t a2, uint32_t a3,
                                         uint32_t b0, uint32_t b1) {
    asm volatile(
        "mma.sync.aligned.m16n8k8.row.col.f32.tf32.tf32.f32 "
        "{%0,%1,%2,%3}, {%4,%5,%6,%7}, {%8,%9}, {%0,%1,%2,%3};"
        : "+f"(d[0]), "+f"(d[1]), "+f"(d[2]), "+f"(d[3])
        : "r"(a0), "r"(a1), "r"(a2), "r"(a3), "r"(b0), "r"(b1));
}

// ---------------------------------------------------------------------------
// Kernel 1: tf32 mma.sync GEMM, partials to g_part, plus distributed pooling
// ---------------------------------------------------------------------------
struct StgRegs {
    float4 a[2][2];   // 2 A-groups x (8 consecutive k as lo/hi float4)
    float4 b[2];      // 1 B-group
};

__device__ __forceinline__ void ldg_chunk(const float* __restrict__ Abase,
                                          const float* __restrict__ Bbase,
                                          int k0, int tid, StgRegs& R) {
    #pragma unroll
    for (int i = 0; i < 2; ++i) {
        int gi = tid + (i << 8);            // 0..511 : A groups (row, 8-k group)
        int row = gi >> 2, j8 = gi & 3;
        const float4* p = reinterpret_cast<const float4*>(
            Abase + (size_t)row * IN_DIM + k0 + j8 * 8);
        R.a[i][0] = p[0];
        R.a[i][1] = p[1];
    }
    {
        int row = tid >> 2, j8 = tid & 3;   // 0..255 : B groups
        const float4* p = reinterpret_cast<const float4*>(
            Bbase + (size_t)row * IN_DIM + k0 + j8 * 8);
        R.b[0] = p[0];
        R.b[1] = p[1];
    }
}

// cols j8*8 + c (c=0..7) -> permuted word (c&3)*8 + 2*j8 + (c>=4)
// => pairs {lo.c, hi.c} at word base + c*8, base = row*SA + 2*j8 (8B aligned).
__device__ __forceinline__ void cvt_sts(float* __restrict__ As,
                                        float* __restrict__ Bs,
                                        int tid, const StgRegs& R) {
    #pragma unroll
    for (int i = 0; i < 2; ++i) {
        int gi = tid + (i << 8);
        int row = gi >> 2, j8 = gi & 3;
        float* base = As + row * SA + 2 * j8;
        float4 lo = R.a[i][0], hi = R.a[i][1];
        *reinterpret_cast<float2*>(base +  0) = make_float2(to_tf32(lo.x), to_tf32(hi.x));
        *reinterpret_cast<float2*>(base +  8) = make_float2(to_tf32(lo.y), to_tf32(hi.y));
        *reinterpret_cast<float2*>(base + 16) = make_float2(to_tf32(lo.z), to_tf32(hi.z));
        *reinterpret_cast<float2*>(base + 24) = make_float2(to_tf32(lo.w), to_tf32(hi.w));
    }
    {
        int row = tid >> 2, j8 = tid & 3;
        float* base = Bs + row * SA + 2 * j8;
        float4 lo = R.b[0], hi = R.b[1];
        *reinterpret_cast<float2*>(base +  0) = make_float2(to_tf32(lo.x), to_tf32(hi.x));
        *reinterpret_cast<float2*>(base +  8) = make_float2(to_tf32(lo.y), to_tf32(hi.y));
        *reinterpret_cast<float2*>(base + 16) = make_float2(to_tf32(lo.z), to_tf32(hi.z));
        *reinterpret_cast<float2*>(base + 24) = make_float2(to_tf32(lo.w), to_tf32(hi.w));
    }
}

__device__ __forceinline__ void compute_chunk(const float* __restrict__ As,
                                              const float* __restrict__ Bs,
                                              int wm32, int wn32, int g, int t,
                                              float acc[2][4][4]) {
    #pragma unroll
    for (int kp = 0; kp < 2; ++kp) {        // k-step pairs (2 x k8 each)
        uint4 A4[2][2], B4[4];
        #pragma unroll
        for (int mm = 0; mm < 2; ++mm)
            #pragma unroll
            for (int h = 0; h < 2; ++h)
                A4[mm][h] = *reinterpret_cast<const uint4*>(
                    As + (wm32 + mm * 16 + g + 8 * h) * SA + t * 8 + kp * 4);
        #pragma unroll
        for (int nt = 0; nt < 4; ++nt)
            B4[nt] = *reinterpret_cast<const uint4*>(
                Bs + (wn32 + nt * 8 + g) * SA + t * 8 + kp * 4);
        #pragma unroll
        for (int k2 = 0; k2 < 2; ++k2) {
            #pragma unroll
            for (int mm = 0; mm < 2; ++mm) {
                uint32_t a0 = k2 ? A4[mm][0].z : A4[mm][0].x;
                uint32_t a2 = k2 ? A4[mm][0].w : A4[mm][0].y;
                uint32_t a1 = k2 ? A4[mm][1].z : A4[mm][1].x;
                uint32_t a3 = k2 ? A4[mm][1].w : A4[mm][1].y;
                #pragma unroll
                for (int nt = 0; nt < 4; ++nt) {
                    uint32_t b0 = k2 ? B4[nt].z : B4[nt].x;
                    uint32_t b1 = k2 ? B4[nt].w : B4[nt].y;
                    mma_tf32(acc[mm][nt], a0, a1, a2, a3, b0, b1);
                }
            }
        }
    }
}

__global__ void __launch_bounds__(GEMM_THREADS, 1)
gemm_kernel(const float* __restrict__ x, const float* __restrict__ weight) {
    extern __shared__ float smem[];
    float* Abuf[2] = { smem, smem + A_STG_WORDS };
    float* Bbuf[2] = { smem + 2 * A_STG_WORDS,
                       smem + 2 * A_STG_WORDS + B_STG_WORDS };

    int tid = threadIdx.x;
    int wid = tid >> 5, lid = tid & 31;
    int g = lid >> 2, t = lid & 3;
    int wm32 = (wid >> 1) * 32;     // warp M offset (4 warps over M)
    int wn32 = (wid & 1) * 32;      // warp N offset (2 warps over N)

    int m = blockIdx.x, e = blockIdx.y, ks = blockIdx.z;
    const float* Abase = weight + ((size_t)e << 20)
                       + (size_t)m * (M_TILE * IN_DIM) + (size_t)ks * K_PER;
    const float* Bbase = x + (size_t)ks * K_PER;

    float acc[2][4][4];
    #pragma unroll
    for (int mm = 0; mm < 2; ++mm)
        #pragma unroll
        for (int nt = 0; nt < 4; ++nt)
            #pragma unroll
            for (int q = 0; q < 4; ++q) acc[mm][nt][q] = 0.f;

    StgRegs R;
    ldg_chunk(Abase, Bbase, 0, tid, R);
    cvt_sts(Abuf[0], Bbuf[0], tid, R);
    __syncthreads();

    for (int tch = 0; tch < NCHUNK; ++tch) {
        if (tch + 1 < NCHUNK)
            ldg_chunk(Abase, Bbase, (tch + 1) * CHUNK_K, tid, R);
        compute_chunk(Abuf[tch & 1], Bbuf[tch & 1], wm32, wn32, g, t, acc);
        if (tch + 1 < NCHUNK) {
            cvt_sts(Abuf[(tch + 1) & 1], Bbuf[(tch + 1) & 1], tid, R);
            __syncthreads();
        }
    }

    // Epilogue: unscaled partial to g_part[m][e][ks][ol][b]
    float* dst = g_part + ((size_t)((m * E_DIM + e) * KSPLIT + ks) << 13);
    #pragma unroll
    for (int mm = 0; mm < 2; ++mm) {
        #pragma unroll
        for (int nt = 0; nt < 4; ++nt) {
            int r0 = wm32 + mm * 16 + g;
            int c0 = wn32 + nt * 8 + 2 * t;
            *reinterpret_cast<float2*>(dst + (size_t)r0 * N_TILE + c0) =
                make_float2(acc[mm][nt][0], acc[mm][nt][1]);
            *reinterpret_cast<float2*>(dst + (size_t)(r0 + 8) * N_TILE + c0) =
                make_float2(acc[mm][nt][2], acc[mm][nt][3]);
        }
    }

    // Distributed pooling: the 64 CTAs with ks==1 each produce one row mean.
    // Runs after the epilogue so it overlaps other CTAs' tails; the reduce
    // kernel (next graph node) is the only consumer, so stream order suffices.
    if (ks == 1 && wid == 0) {
        int b = m * E_DIM + e;                  // 0..63, unique per (m,e)
        const float* xr = x + (size_t)b * IN_DIM;
        float s = 0.f;
        #pragma unroll 8
        for (int k = lid; k < IN_DIM; k += 32) s += xr[k];
        #pragma unroll
        for (int o = 16; o > 0; o >>= 1) s += __shfl_xor_sync(0xFFFFFFFFu, s, o);
        if (lid == 0) g_pooled[b] = s * (1.0f / IN_DIM);
    }
}

// ---------------------------------------------------------------------------
// Kernel 2: c[b,e] from g_pooled (tiny, redundant per block), then
//           y[b,o] = sum_e c[b,e] * (part[m,e,0,ol,b] + part[m,e,1,ol,b])
// ---------------------------------------------------------------------------
__global__ void reduce_kernel(float* __restrict__ y,
                              const float* __restrict__ align_conv,
                              const float* __restrict__ W_ih,
                              const float* __restrict__ b_ih,
                              const float* __restrict__ b_hh,
                              const float* __restrict__ W_att,
                              const float* __restrict__ b_att) {
    __shared__ float cs[B_DIM * E_DIM];
    int tid = threadIdx.x;
    if (tid < B_DIM) {
        float p = g_pooled[tid];
        float r[H_DIM];
        #pragma unroll
        for (int j = 0; j < H_DIM; ++j)
            r[j] = fmaxf(tanhf(p * W_ih[j] + b_ih[j] + b_hh[j]), 0.f);
        float a[E_DIM];
        float mx = -1e30f;
        #pragma unroll
        for (int eo = 0; eo < E_DIM; ++eo) {
            float s = b_att[eo];
            #pragma unroll
            for (int j = 0; j < H_DIM; ++j) s = fmaf(W_att[eo * H_DIM + j], r[j], s);
            a[eo] = s;
            mx = fmaxf(mx, s);
        }
        float se = 0.f;
        #pragma unroll
        for (int eo = 0; eo < E_DIM; ++eo) { a[eo] = expf(a[eo] - mx); se += a[eo]; }
        float inv = 1.f / se;
        #pragma unroll
        for (int eo = 0; eo < E_DIM; ++eo) {
            float ce = 0.f;
            #pragma unroll
            for (int f = 0; f < E_DIM; ++f)
                ce = fmaf(a[f] * inv, align_conv[f * E_DIM + eo], ce);
            cs[tid * E_DIM + eo] = ce;
        }
    }
    __syncthreads();

    int idx = blockIdx.x * blockDim.x + tid;   // 64 blocks * 1024 = 65536
    int o  = idx >> 6;
    int b  = idx & 63;
    int mm = o >> 7;
    int ol = o & 127;
    const float* pbase = g_part + (size_t)ol * N_TILE + b;
    float acc = 0.f;
    #pragma unroll
    for (int e = 0; e < E_DIM; ++e) {
        float w = cs[b * E_DIM + e];
        const float* p = pbase + ((size_t)((mm * E_DIM + e) * KSPLIT) << 13);
        acc = fmaf(w, p[0] + p[8192], acc);
    }
    y[b * OUT_DIM + o] = acc;
}

// ---------------------------------------------------------------------------
// Launch: 2 graph nodes (gemm -> reduce)
// ---------------------------------------------------------------------------
extern "C" void kernel_launch(void* const* d_in, const int* in_sizes, int n_in,
                              void* d_out, int out_size) {
    const float* x          = (const float*)d_in[0];
    const float* weight     = (const float*)d_in[1];
    const float* align_conv = (const float*)d_in[2];
    const float* W_ih       = (const float*)d_in[3];
    // d_in[4] = W_hh: h0 = 0, contributes nothing -- intentionally unused.
    const float* b_ih       = (const float*)d_in[5];
    const float* b_hh       = (const float*)d_in[6];
    const float* W_att      = (const float*)d_in[7];
    const float* b_att      = (const float*)d_in[8];
    float* y = (float*)d_out;

    cudaFuncSetAttribute(gemm_kernel,
                         cudaFuncAttributeMaxDynamicSharedMemorySize, SMEM_BYTES);

    gemm_kernel<<<dim3(8, E_DIM, KSPLIT), GEMM_THREADS, SMEM_BYTES>>>(x, weight);
    reduce_kernel<<<64, 1024>>>(y, align_conv, W_ih, b_ih, b_hh, W_att, b_att);
}